// round 6
// baseline (speedup 1.0000x reference)
#include <cuda_runtime.h>
#include <cstdint>

// Shapes (fixed by the problem)
#define S_IN   2048
#define S_T    2048
#define BATCH  8
#define HID    64

#define TM     16            // t-rows per CTA
#define SC     256           // s-chunk size
#define NCHUNK (S_IN / SC)   // 8
#define BPITCH 264           // sBT pitch (floats), 256 + 8 pad
#define LPITCH 68            // staging pitch for sWT (linear stage)

// SMEM layout (floats):
//   sS  [TM][2048]       scores          32768
//   sBT [64][BPITCH]     input^T chunk   16896
//   sAT [64][16]         lin out (h-major) 1024
#define SS_FLOATS  (TM * S_IN)
#define BT_FLOATS  (HID * BPITCH)
#define AT_FLOATS  (HID * 16)
#define SMEM_FLOATS (SS_FLOATS + BT_FLOATS + AT_FLOATS)

typedef unsigned long long ull;

__device__ __forceinline__ ull pack_dup(float x) {
    ull r; asm("mov.b64 %0, {%1, %2};" : "=l"(r) : "f"(x), "f"(x)); return r;
}
__device__ __forceinline__ void unpack2(ull v, float& lo, float& hi) {
    asm("mov.b64 {%0, %1}, %2;" : "=f"(lo), "=f"(hi) : "l"(v));
}
__device__ __forceinline__ void fma2(ull& acc, ull a, ull b) {
    asm("fma.rn.f32x2 %0, %1, %2, %0;" : "+l"(acc) : "l"(a), "l"(b));
}

__device__ __forceinline__ float warp_sum(float v) {
    v += __shfl_xor_sync(0xffffffffu, v, 16);
    v += __shfl_xor_sync(0xffffffffu, v, 8);
    v += __shfl_xor_sync(0xffffffffu, v, 4);
    v += __shfl_xor_sync(0xffffffffu, v, 2);
    v += __shfl_xor_sync(0xffffffffu, v, 1);
    return v;
}
__device__ __forceinline__ float warp_max(float v) {
    v = fmaxf(v, __shfl_xor_sync(0xffffffffu, v, 16));
    v = fmaxf(v, __shfl_xor_sync(0xffffffffu, v, 8));
    v = fmaxf(v, __shfl_xor_sync(0xffffffffu, v, 4));
    v = fmaxf(v, __shfl_xor_sync(0xffffffffu, v, 2));
    v = fmaxf(v, __shfl_xor_sync(0xffffffffu, v, 1));
    return v;
}

__global__ void __launch_bounds__(256, 1)
attn_fused_kernel(const float* __restrict__ inp,        // (S_IN, B, H)
                  const float* __restrict__ tgt,        // (S_T, B, H)
                  const unsigned char* __restrict__ msk,// (B, S_T, S_IN) bool
                  const float* __restrict__ Wm,         // (H, H)  W[o][h]
                  const float* __restrict__ bias,       // (H)
                  float* __restrict__ out)              // (B, S_T, S_IN)
{
    extern __shared__ float sm[];
    float* sS  = sm;                        // TM * 2048
    float* sBT = sm + SS_FLOATS;            // [h][s] transposed input chunk
    float* sAT = sBT + BT_FLOATS;           // [h][r] linear output, transposed

    const int tid = threadIdx.x;
    const int b   = blockIdx.x >> 7;          // 8 batches
    const int t0  = (blockIdx.x & 127) << 4;  // tile of 16 t-rows

    // ---------------- prefetch chunk 0 into registers ----------------
    // thread t owns s-row (c*SC + t): 64 contiguous floats = 16 float4
    float4 pf[16];
    {
        const float4* src = reinterpret_cast<const float4*>(
            inp + ((size_t)(tid * BATCH + b)) * HID);
        #pragma unroll
        for (int i = 0; i < 16; ++i) pf[i] = src[i];
    }

    // ---------------- stage W (transposed) + target tile in sS region ----------------
    float* sWT = sS;                  // 64 * LPITCH floats
    float* sTg = sS + HID * LPITCH;   // TM * 64 floats
    {
        const int o  = tid >> 2;
        const int hq = (tid & 3) * 16;
        #pragma unroll
        for (int k = 0; k < 4; ++k) {
            float4 wv = *reinterpret_cast<const float4*>(Wm + o * HID + hq + 4 * k);
            sWT[(hq + 4 * k + 0) * LPITCH + o] = wv.x;
            sWT[(hq + 4 * k + 1) * LPITCH + o] = wv.y;
            sWT[(hq + 4 * k + 2) * LPITCH + o] = wv.z;
            sWT[(hq + 4 * k + 3) * LPITCH + o] = wv.w;
        }
        const int r  = tid >> 4;
        const int hh = (tid & 15) * 4;
        *reinterpret_cast<float4*>(sTg + r * HID + hh) =
            *reinterpret_cast<const float4*>(tgt + ((size_t)((t0 + r) * BATCH + b)) * HID + hh);
    }
    __syncthreads();

    // ---------------- sAT[o][r] = (target_tile @ W^T + bias)[r][o] ----------------
    {
        const int r  = tid >> 4;
        const int o0 = (tid & 15) * 4;
        float4 acc = *reinterpret_cast<const float4*>(bias + o0);
        #pragma unroll
        for (int h = 0; h < HID; ++h) {
            const float  tv = sTg[r * HID + h];
            const float4 wv = *reinterpret_cast<const float4*>(sWT + h * LPITCH + o0);
            acc.x += tv * wv.x;
            acc.y += tv * wv.y;
            acc.z += tv * wv.z;
            acc.w += tv * wv.w;
        }
        sAT[(o0 + 0) * 16 + r] = acc.x;
        sAT[(o0 + 1) * 16 + r] = acc.y;
        sAT[(o0 + 2) * 16 + r] = acc.z;
        sAT[(o0 + 3) * 16 + r] = acc.w;
    }
    // (first loop __syncthreads() makes sAT visible before it is read)

    const int wid  = tid >> 5;
    const int lane = tid & 31;
    const int rg   = wid >> 2;                 // row group: rows rg*8 .. rg*8+7
    const int c2   = (wid & 3) * 64 + 2 * lane;// first of 2 s-cols in chunk

    // ---------------- main loop over s-chunks ----------------
    for (int c = 0; c < NCHUNK; ++c) {
        __syncthreads();   // prev compute done reading sBT; sAT visible (c==0)
        // transpose-store prefetched chunk into sBT[h][s]
        #pragma unroll
        for (int i = 0; i < 16; ++i) {
            sBT[(4 * i + 0) * BPITCH + tid] = pf[i].x;
            sBT[(4 * i + 1) * BPITCH + tid] = pf[i].y;
            sBT[(4 * i + 2) * BPITCH + tid] = pf[i].z;
            sBT[(4 * i + 3) * BPITCH + tid] = pf[i].w;
        }
        __syncthreads();
        // prefetch next chunk (latency hidden by compute below)
        if (c + 1 < NCHUNK) {
            const float4* src = reinterpret_cast<const float4*>(
                inp + ((size_t)(((c + 1) * SC + tid) * BATCH + b)) * HID);
            #pragma unroll
            for (int i = 0; i < 16; ++i) pf[i] = src[i];
        }

        // 8 rows x 2 cols per lane, rows paired into f32x2 accumulators
        ull acc[4][2];
        #pragma unroll
        for (int p = 0; p < 4; ++p) { acc[p][0] = 0ull; acc[p][1] = 0ull; }

        const float* aBase = sAT + rg * 8;
        const float* bBase = sBT + c2;
        #pragma unroll 8
        for (int h = 0; h < HID; ++h) {
            // rows rg*8..+3 and +4..+7 as two (lo,hi) f32x2 pairs each (broadcast)
            const ulonglong2 aP0 = *reinterpret_cast<const ulonglong2*>(aBase + h * 16);
            const ulonglong2 aP1 = *reinterpret_cast<const ulonglong2*>(aBase + h * 16 + 4);
            const float2 bv = *reinterpret_cast<const float2*>(bBase + h * BPITCH);
            const ull b0 = pack_dup(bv.x);
            const ull b1 = pack_dup(bv.y);
            fma2(acc[0][0], aP0.x, b0);  fma2(acc[0][1], aP0.x, b1);
            fma2(acc[1][0], aP0.y, b0);  fma2(acc[1][1], aP0.y, b1);
            fma2(acc[2][0], aP1.x, b0);  fma2(acc[2][1], aP1.x, b1);
            fma2(acc[3][0], aP1.y, b0);  fma2(acc[3][1], aP1.y, b1);
        }
        // store scores: acc[p][c] holds rows (rg*8+2p, rg*8+2p+1), col c2+c
        float* dst = sS + c * SC + c2;
        #pragma unroll
        for (int p = 0; p < 4; ++p) {
            float lo0, hi0, lo1, hi1;
            unpack2(acc[p][0], lo0, hi0);
            unpack2(acc[p][1], lo1, hi1);
            float* d0 = dst + (rg * 8 + 2 * p) * S_IN;
            *reinterpret_cast<float2*>(d0)        = make_float2(lo0, lo1);
            *reinterpret_cast<float2*>(d0 + S_IN) = make_float2(hi0, hi1);
        }
    }
    __syncthreads();

    // ---------------- fused epilogue: mean -> abs/mask -> max -> exp -> normalize ----------------
    const float NEG_INF = __int_as_float(0xff800000);
    #pragma unroll
    for (int rr = 0; rr < 2; ++rr) {
        const int r = wid * 2 + rr;                  // warp handles rows 2w, 2w+1
        float* row = sS + r * S_IN;
        const size_t gbase = ((size_t)(b * S_T + (t0 + r))) * S_IN;

        // mean over s
        float s = 0.f;
        #pragma unroll
        for (int i = 0; i < 16; ++i) {
            const float4 v = *reinterpret_cast<const float4*>(row + i * 128 + lane * 4);
            s += (v.x + v.y) + (v.z + v.w);
        }
        s = warp_sum(s);
        const float mean = s * (1.0f / 2048.0f);

        // y = |x - mean|, apply mask (-inf), track max
        float m = NEG_INF;
        #pragma unroll
        for (int i = 0; i < 16; ++i) {
            float4 v = *reinterpret_cast<const float4*>(row + i * 128 + lane * 4);
            v.x = fabsf(v.x - mean);
            v.y = fabsf(v.y - mean);
            v.z = fabsf(v.z - mean);
            v.w = fabsf(v.w - mean);
            const unsigned int mk = *reinterpret_cast<const unsigned int*>(
                msk + gbase + i * 128 + lane * 4);
            if (mk & 0x000000FFu) v.x = NEG_INF;
            if (mk & 0x0000FF00u) v.y = NEG_INF;
            if (mk & 0x00FF0000u) v.z = NEG_INF;
            if (mk & 0xFF000000u) v.w = NEG_INF;
            *reinterpret_cast<float4*>(row + i * 128 + lane * 4) = v;
            m = fmaxf(m, fmaxf(fmaxf(v.x, v.y), fmaxf(v.z, v.w)));
        }
        m = warp_max(m);

        // e = exp(y - max); sum
        float l = 0.f;
        #pragma unroll
        for (int i = 0; i < 16; ++i) {
            float4 v = *reinterpret_cast<const float4*>(row + i * 128 + lane * 4);
            v.x = __expf(v.x - m);
            v.y = __expf(v.y - m);
            v.z = __expf(v.z - m);
            v.w = __expf(v.w - m);
            *reinterpret_cast<float4*>(row + i * 128 + lane * 4) = v;
            l += (v.x + v.y) + (v.z + v.w);
        }
        l = warp_sum(l);
        const float inv = 1.0f / l;

        // write normalized probabilities
        #pragma unroll
        for (int i = 0; i < 16; ++i) {
            float4 v = *reinterpret_cast<const float4*>(row + i * 128 + lane * 4);
            v.x *= inv; v.y *= inv; v.z *= inv; v.w *= inv;
            *reinterpret_cast<float4*>(out + gbase + i * 128 + lane * 4) = v;
        }
    }
}

extern "C" void kernel_launch(void* const* d_in, const int* in_sizes, int n_in,
                              void* d_out, int out_size)
{
    const float*         inp  = (const float*)d_in[0];
    const float*         tgt  = (const float*)d_in[1];
    const unsigned char* msk  = (const unsigned char*)d_in[2];
    const float*         Wm   = (const float*)d_in[3];
    const float*         bias = (const float*)d_in[4];
    float*               out  = (float*)d_out;

    const int smem_bytes = SMEM_FLOATS * (int)sizeof(float); // 202752 B
    cudaFuncSetAttribute(attn_fused_kernel,
                         cudaFuncAttributeMaxDynamicSharedMemorySize, smem_bytes);

    dim3 grid(BATCH * (S_T / TM));  // 1024 CTAs
    dim3 block(256);
    attn_fused_kernel<<<grid, block, smem_bytes>>>(inp, tgt, msk, Wm, bias, out);
}